// round 9
// baseline (speedup 1.0000x reference)
#include <cuda_runtime.h>
#include <cuda_bf16.h>
#include <cstdint>

// BFPActivation3D: block floating-point quantization over channel blocks.
// Shapes (fixed): activations [N=8, C=64, D=32, H=64, W=64] fp32,
// mantissa = 7, blk = 16. Blocks run along C at stride S = D*H*W.
//
// Per block of 16 channel values x_c at one spatial position:
//   maxabs = max |x_c|
//   se     = floor(log2(maxabs))            (== frexp exponent - 1)
//   quantum = 2^(se-6);  q_c = clip(rint(x_c/quantum), -127, 127) * quantum
//   all-zero block -> 0
// Power-of-two scales are exact; rintf = half-to-even = jnp.round.
// rel_err == 0.0 verified on hardware (R5, R7, R8).
//
// Evidence so far: DRAM pinned ~81% across occ 21/31/54%, LDG.64 vs LDG.128,
// with/without streaming hints. R9 lever: persistent grid (148x3 CTAs,
// grid-stride over 4096 tiles) to eliminate ~9 waves of CTA drain/relaunch
// and keep the load stream continuously behind the store stream.

namespace {
constexpr int N_      = 8;
constexpr int C_      = 64;
constexpr int S_      = 32 * 64 * 64;   // D*H*W = 131072
constexpr int BLK     = 16;             // channels per block
constexpr int NBLK    = C_ / BLK;       // 4
constexpr int S4      = S_ / 4;         // float4 positions per (n, cblk) = 32768
constexpr int THREADS = 256;
constexpr int NTILES  = N_ * NBLK * S4 / THREADS;  // 4096 tiles of 256 threads
constexpr int SMS     = 148;
constexpr int CTAS    = SMS * 3;        // persistent grid: 3 CTAs/SM
}

__global__ __launch_bounds__(THREADS, 3)
void bfp3d_kernel(const float* __restrict__ in, float* __restrict__ out) {
    for (int tile = blockIdx.x; tile < NTILES; tile += CTAS) {
        const int t = tile * THREADS + (int)threadIdx.x;
        // t -> (n, cblk, s4). S4 = 2^15, NBLK = 4.
        const int s4   = t & (S4 - 1);
        const int cblk = (t >> 15) & (NBLK - 1);
        const int n    = t >> 17;

        const int base = (n * C_ + cblk * BLK) * S_ + s4 * 4;   // < 2^27
        const float4* __restrict__ ip = reinterpret_cast<const float4*>(in + base);
        float4* __restrict__ op = reinterpret_cast<float4*>(out + base);

        // 16 strided float4 loads: per warp each is a contiguous 512B segment.
        float x[4][BLK];   // [lane within float4][channel]
        #pragma unroll
        for (int c = 0; c < BLK; c++) {
            float4 v = __ldcs(ip + c * S4);
            x[0][c] = v.x; x[1][c] = v.y; x[2][c] = v.z; x[3][c] = v.w;
        }

        #pragma unroll
        for (int l = 0; l < 4; l++) {
            float m = fabsf(x[l][0]);
            #pragma unroll
            for (int c = 1; c < BLK; c++) m = fmaxf(m, fabsf(x[l][c]));

            // shared exponent = floor(log2(m)) for normal m
            const int se = (int)((__float_as_uint(m) >> 23) & 0xFFu) - 127;

            // exact power-of-two scales
            const float rscale  = ldexpf(1.0f, 6 - se);   // 1/quantum
            const float quantum = ldexpf(1.0f, se - 6);

            const bool nz = (m > 0.0f);
            #pragma unroll
            for (int c = 0; c < BLK; c++) {
                float q = rintf(x[l][c] * rscale);        // half-to-even
                q = fminf(fmaxf(q, -127.0f), 127.0f);
                q *= quantum;
                x[l][c] = nz ? q : 0.0f;
            }
        }

        #pragma unroll
        for (int c = 0; c < BLK; c++) {
            float4 v;
            v.x = x[0][c]; v.y = x[1][c]; v.z = x[2][c]; v.w = x[3][c];
            __stcs(op + c * S4, v);   // streaming store: no reuse
        }
    }
}

extern "C" void kernel_launch(void* const* d_in, const int* in_sizes, int n_in,
                              void* d_out, int out_size) {
    const float* in = (const float*)d_in[0];   // activations, 67,108,864 floats
    float* out = (float*)d_out;
    (void)in_sizes; (void)n_in; (void)out_size;   // mantissa=7, blk=16 fixed

    bfp3d_kernel<<<CTAS, THREADS>>>(in, out);
}

// round 10
// speedup vs baseline: 1.1435x; 1.1435x over previous
#include <cuda_runtime.h>
#include <cuda_bf16.h>
#include <cstdint>

// BFPActivation3D: block floating-point quantization over channel blocks.
// Shapes (fixed): activations [N=8, C=64, D=32, H=64, W=64] fp32,
// mantissa = 7, blk = 16. Blocks run along C at stride S = D*H*W.
//
// Per block of 16 channel values x_c at one spatial position:
//   maxabs = max |x_c|
//   se     = floor(log2(maxabs))            (== frexp exponent - 1)
//   quantum = 2^(se-6);  q_c = clip(rint(x_c/quantum), -127, 127) * quantum
//   all-zero block -> 0
// Power-of-two scales are exact; rintf = half-to-even = jnp.round.
// rel_err == 0.0 verified on hardware (R5, R7, R8, R9).
//
// FINAL CONFIG (R7, best measured: 74.3us kernel / 82.0us harness, DRAM 81.6%).
// Session evidence: DRAM pinned ~81.5% of spec across occ {21,31,54}%,
// LDG.64 vs LDG.128, and cache policies; persistent grid regressed (WAR
// serialization of cross-iteration load batches). ~81.5% is the R/W-mixed
// stream DRAM turnaround floor for this op on B300 -> this is the roofline.

namespace {
constexpr int N_      = 8;
constexpr int C_      = 64;
constexpr int S_      = 32 * 64 * 64;   // D*H*W = 131072
constexpr int BLK     = 16;             // channels per block
constexpr int NBLK    = C_ / BLK;       // 4
constexpr int S4      = S_ / 4;         // float4 positions per (n, cblk) = 32768
constexpr int THREADS = 256;
constexpr int TOTAL_T = N_ * NBLK * S4; // 1,048,576 threads
}

__global__ __launch_bounds__(THREADS, 3)
void bfp3d_kernel(const float* __restrict__ in, float* __restrict__ out) {
    const int t = blockIdx.x * THREADS + threadIdx.x;
    // t -> (n, cblk, s4). S4 = 2^15, NBLK = 4.
    const int s4   = t & (S4 - 1);
    const int cblk = (t >> 15) & (NBLK - 1);
    const int n    = t >> 17;

    const int base = (n * C_ + cblk * BLK) * S_ + s4 * 4;   // < 2^27, int ok
    const float4* __restrict__ ip = reinterpret_cast<const float4*>(in + base);
    float4* __restrict__ op = reinterpret_cast<float4*>(out + base);

    // 16 strided float4 loads: across a warp each is a contiguous 512B segment
    // (perfectly coalesced); per-thread MLP = 16 hides DRAM latency.
    // Streaming (evict-first) hint: data is touched exactly once.
    float x[4][BLK];   // [lane within float4][channel]
    #pragma unroll
    for (int c = 0; c < BLK; c++) {
        float4 v = __ldcs(ip + c * S4);
        x[0][c] = v.x; x[1][c] = v.y; x[2][c] = v.z; x[3][c] = v.w;
    }

    #pragma unroll
    for (int l = 0; l < 4; l++) {
        // blockwise max-abs
        float m = fabsf(x[l][0]);
        #pragma unroll
        for (int c = 1; c < BLK; c++) m = fmaxf(m, fabsf(x[l][c]));

        // shared exponent = floor(log2(m)) for normal m
        const int se = (int)((__float_as_uint(m) >> 23) & 0xFFu) - 127;

        // exact power-of-two scales (integer exponent -> exact construction)
        const float rscale  = ldexpf(1.0f, 6 - se);   // 1/quantum
        const float quantum = ldexpf(1.0f, se - 6);

        const bool nz = (m > 0.0f);
        #pragma unroll
        for (int c = 0; c < BLK; c++) {
            float q = rintf(x[l][c] * rscale);          // half-to-even
            q = fminf(fmaxf(q, -127.0f), 127.0f);
            q *= quantum;
            x[l][c] = nz ? q : 0.0f;
        }
    }

    #pragma unroll
    for (int c = 0; c < BLK; c++) {
        float4 v;
        v.x = x[0][c]; v.y = x[1][c]; v.z = x[2][c]; v.w = x[3][c];
        __stcs(op + c * S4, v);   // streaming store: no reuse, evict first
    }
}

extern "C" void kernel_launch(void* const* d_in, const int* in_sizes, int n_in,
                              void* d_out, int out_size) {
    const float* in = (const float*)d_in[0];   // activations, 67,108,864 floats
    float* out = (float*)d_out;
    (void)in_sizes; (void)n_in; (void)out_size;   // mantissa=7, blk=16 fixed

    bfp3d_kernel<<<TOTAL_T / THREADS, THREADS>>>(in, out);
}

// round 12
// speedup vs baseline: 1.1471x; 1.0031x over previous
#include <cuda_runtime.h>
#include <cuda_bf16.h>
#include <cstdint>

// BFPActivation3D: block floating-point quantization over channel blocks.
// Shapes (fixed): activations [N=8, C=64, D=32, H=64, W=64] fp32,
// mantissa = 7, blk = 16. Blocks run along C at stride S = D*H*W.
//
// Per block of 16 channel values x_c at one spatial position:
//   maxabs = max |x_c|
//   se     = floor(log2(maxabs))            (== frexp exponent - 1)
//   quantum = 2^(se-6);  q_c = clip(rint(x_c/quantum), -127, 127) * quantum
//   all-zero block -> 0
// Power-of-two scales are exact; rintf = half-to-even = jnp.round.
// rel_err == 0.0 verified on hardware (R5, R7, R8, R9, R10).
//
// FINAL CONFIG (R7 structure; best measured 74.3us kernel / 82.0us harness).
// Session evidence: DRAM pinned at 80-81.6% of spec (~6.45 TB/s) across
// occ {21,31,54}%, LDG.64 vs LDG.128, cache policies; persistent grid
// regressed (WAR serialization of cross-iteration load batches). The 1:1
// read/write mixed stream's DRAM turnaround is the roofline — no SM-side
// configuration moves it. This kernel sits on that roof.
//
// Micro-edge: power-of-two scales built directly from the IEEE exponent
// field ((bias+k)<<23) instead of ldexpf — shortens the max->rint dependency
// chain by a few ALU ops. For m==0 (or denormal) the constructed scale bits
// are garbage, but the nz select forces those lanes to 0.0f and the garbage
// value is a finite float (exp-field arithmetic stays within the u32), so no
// NaN/Inf propagates into the selected-away computation.
//
// (R11 bench was a broker-side container failure — this is an unchanged
// resubmission, not a mutation.)

namespace {
constexpr int N_      = 8;
constexpr int C_      = 64;
constexpr int S_      = 32 * 64 * 64;   // D*H*W = 131072
constexpr int BLK     = 16;             // channels per block
constexpr int NBLK    = C_ / BLK;       // 4
constexpr int S4      = S_ / 4;         // float4 positions per (n, cblk) = 32768
constexpr int THREADS = 256;
constexpr int TOTAL_T = N_ * NBLK * S4; // 1,048,576 threads
}

__global__ __launch_bounds__(THREADS, 3)
void bfp3d_kernel(const float* __restrict__ in, float* __restrict__ out) {
    const int t = blockIdx.x * THREADS + threadIdx.x;
    // t -> (n, cblk, s4). S4 = 2^15, NBLK = 4.
    const int s4   = t & (S4 - 1);
    const int cblk = (t >> 15) & (NBLK - 1);
    const int n    = t >> 17;

    const int base = (n * C_ + cblk * BLK) * S_ + s4 * 4;   // < 2^27, int ok
    const float4* __restrict__ ip = reinterpret_cast<const float4*>(in + base);
    float4* __restrict__ op = reinterpret_cast<float4*>(out + base);

    // 16 strided float4 loads: across a warp each is a contiguous 512B segment
    // (perfectly coalesced); per-thread MLP = 16 hides DRAM latency.
    // Streaming (evict-first) hint: data is touched exactly once.
    float x[4][BLK];   // [lane within float4][channel]
    #pragma unroll
    for (int c = 0; c < BLK; c++) {
        float4 v = __ldcs(ip + c * S4);
        x[0][c] = v.x; x[1][c] = v.y; x[2][c] = v.z; x[3][c] = v.w;
    }

    #pragma unroll
    for (int l = 0; l < 4; l++) {
        // blockwise max-abs
        float m = fabsf(x[l][0]);
        #pragma unroll
        for (int c = 1; c < BLK; c++) m = fmaxf(m, fabsf(x[l][c]));

        // Exponent field of m: eb = se + 127 where se = floor(log2(m)).
        // rscale = 2^(6-se)  -> exp field (6-se)+127 = 260 - eb
        // quantum = 2^(se-6) -> exp field (se-6)+127 = eb - 6
        const uint32_t eb = (__float_as_uint(m) >> 23);   // fabs => bits 0..7
        const float rscale  = __uint_as_float((260u - eb) << 23);
        const float quantum = __uint_as_float((eb - 6u) << 23);

        const bool nz = (m > 0.0f);
        #pragma unroll
        for (int c = 0; c < BLK; c++) {
            float q = rintf(x[l][c] * rscale);          // half-to-even
            q = fminf(fmaxf(q, -127.0f), 127.0f);
            q *= quantum;
            x[l][c] = nz ? q : 0.0f;
        }
    }

    #pragma unroll
    for (int c = 0; c < BLK; c++) {
        float4 v;
        v.x = x[0][c]; v.y = x[1][c]; v.z = x[2][c]; v.w = x[3][c];
        __stcs(op + c * S4, v);   // streaming store: no reuse, evict first
    }
}

extern "C" void kernel_launch(void* const* d_in, const int* in_sizes, int n_in,
                              void* d_out, int out_size) {
    const float* in = (const float*)d_in[0];   // activations, 67,108,864 floats
    float* out = (float*)d_out;
    (void)in_sizes; (void)n_in; (void)out_size;   // mantissa=7, blk=16 fixed

    bfp3d_kernel<<<TOTAL_T / THREADS, THREADS>>>(in, out);
}